// round 4
// baseline (speedup 1.0000x reference)
#include <cuda_runtime.h>
#include <cstdint>
#include <math.h>

#define T_STEPS 512
#define B_ROWS  64
#define F_DIM   256
#define U_DIM   1024
#define NB      128
#define NT      256
#define KT      128
#define AS_STRIDE 132          // padded floats per A row (conflict-free)

#define AS_BYTES (2 * B_ROWS * AS_STRIDE * 4)      // 67584
#define WS_BYTES (2 * 64 * 64 * 4)                 // 32768
#define SMEM_TOTAL (AS_BYTES + WS_BYTES)           // 100352

// ---------------- persistent device state ----------------
__device__ float g_Wr[(1280 + 2048 + 2048) * 4096]; // k-paired gate-interleaved
__device__ float g_h[2][3][B_ROWS][U_DIM];
__device__ float g_c[2][3][B_ROWS][U_DIM];
__device__ float g_emit[B_ROWS * F_DIM];

__device__ unsigned g_bar_count = 0;
__device__ volatile unsigned g_bar_gen = 0;

// Wp[k>>1][ (u*4+g)*2 + (k&1) ]  (row stride 8192 floats)
__global__ void reorder_w(const float* __restrict__ W, float* __restrict__ Wr, int total) {
    int idx = blockIdx.x * blockDim.x + threadIdx.x;
    if (idx >= total) return;
    int k = idx >> 12, n = idx & 4095;
    int g = n >> 10, u = n & 1023;
    Wr[((size_t)(k >> 1) << 13) + (((u << 2) + g) << 1) + (k & 1)] = W[idx];
}

// ---------------- grid-wide barrier ----------------
__device__ __forceinline__ void grid_barrier() {
    __syncthreads();
    if (threadIdx.x == 0) {
        __threadfence();
        unsigned gen = g_bar_gen;
        if (atomicAdd(&g_bar_count, 1u) == (unsigned)(NB - 1)) {
            g_bar_count = 0;
            __threadfence();
            g_bar_gen = gen + 1u;
        } else {
            while (g_bar_gen == gen) { }
        }
    }
    __syncthreads();
    __threadfence();  // acquire: flush stale L1
}

// ---------------- helpers ----------------
__device__ __forceinline__ float sigf(float x) { return 1.0f / (1.0f + expf(-x)); }

__device__ __forceinline__ void ffma2(unsigned long long& acc,
                                      unsigned long long a, unsigned long long b) {
    asm("fma.rn.f32x2 %0, %1, %2, %0;" : "+l"(acc) : "l"(a), "l"(b));
}
__device__ __forceinline__ float sumf2(unsigned long long v) {
    float lo = __uint_as_float((unsigned)(v & 0xffffffffu));
    float hi = __uint_as_float((unsigned)(v >> 32));
    return lo + hi;
}
__device__ __forceinline__ void cpa16(uint32_t s, const void* g) {
    asm volatile("cp.async.cg.shared.global [%0], [%1], 16;\n" :: "r"(s), "l"(g));
}
__device__ __forceinline__ void cp_commit() { asm volatile("cp.async.commit_group;\n"); }
template<int N> __device__ __forceinline__ void cp_wait() {
    asm volatile("cp.async.wait_group %0;\n" :: "n"(N));
}

// ---------------- LSTM layer phase ----------------
// CTA: 64 rows x 32 interleaved cols. Thread: 2 rows x 4 cols (= 4 gates of unit u).
__device__ __forceinline__ void layer_phase(
    const float* __restrict__ A0, int lda0, int Kin,
    const float* __restrict__ Hold,
    const float* __restrict__ Wr,        // k-paired layout, row stride 8192
    const float* __restrict__ bias,      // original [4096]
    const float* __restrict__ Cold,
    float* __restrict__ Cnew, float* __restrict__ Hnew,
    float* Ash, float* Wsh, uint32_t as_u32, uint32_t ws_u32,
    int cta, int tid)
{
    const int lane = tid & 31, warp = tid >> 5;
    const int ct = lane & 7;             // col-thread: unit u = cta*8+ct
    const int rt = lane >> 3;            // row-thread
    const int r0 = warp * 8 + rt * 2;
    const int c0 = ct * 4;               // local col base
    const int ntiles = (Kin + U_DIM) / KT;

    unsigned long long acc[2][4];
    #pragma unroll
    for (int r = 0; r < 2; r++)
        #pragma unroll
        for (int j = 0; j < 4; j++) acc[r][j] = 0ull;

    // ---- prefetch tile 0 ----
    {
        const float* Asrc = (0 < Kin) ? A0 : Hold;
        const int lda = (0 < Kin) ? lda0 : U_DIM;
        #pragma unroll
        for (int q = 0; q < 8; q++) {
            int idx = tid + q * NT, r = idx >> 5, c4 = idx & 31;
            cpa16(as_u32 + (unsigned)((r * AS_STRIDE + c4 * 4) * 4),
                  Asrc + (size_t)r * lda + c4 * 4);
        }
        const float* Wt = Wr + (size_t)cta * 64;
        #pragma unroll
        for (int q = 0; q < 4; q++) {
            int idx = tid + q * NT, r = idx >> 4, c4 = idx & 15;
            cpa16(ws_u32 + (unsigned)((r * 64 + c4 * 4) * 4),
                  Wt + (size_t)r * 8192 + c4 * 4);
        }
        cp_commit();
    }

    for (int j = 0; j < ntiles; j++) {
        const int bc = j & 1;            // compute buffer
        // prefetch tile j+1 into buffer (j+1)&1
        if (j + 1 < ntiles) {
            const int kb = (j + 1) * KT;
            const int bp = (j + 1) & 1;
            const float* Asrc; int lda, koff;
            if (kb < Kin) { Asrc = A0; lda = lda0; koff = kb; }
            else          { Asrc = Hold; lda = U_DIM; koff = kb - Kin; }
            #pragma unroll
            for (int q = 0; q < 8; q++) {
                int idx = tid + q * NT, r = idx >> 5, c4 = idx & 31;
                cpa16(as_u32 + (unsigned)(((bp * B_ROWS + r) * AS_STRIDE + c4 * 4) * 4),
                      Asrc + (size_t)r * lda + koff + c4 * 4);
            }
            const float* Wt = Wr + ((size_t)(kb >> 1)) * 8192 + cta * 64;
            #pragma unroll
            for (int q = 0; q < 4; q++) {
                int idx = tid + q * NT, r = idx >> 4, c4 = idx & 15;
                cpa16(ws_u32 + (unsigned)(((bp * 64 + r) * 64 + c4 * 4) * 4),
                      Wt + (size_t)r * 8192 + c4 * 4);
            }
            cp_commit();
            cp_wait<1>();
        } else {
            cp_wait<0>();
        }
        __syncthreads();

        const float* Asb = Ash + bc * B_ROWS * AS_STRIDE;
        const float* Wsb = Wsh + bc * 64 * 64;

        #pragma unroll 4
        for (int k4 = 0; k4 < KT; k4 += 4) {
            const int kp = k4 >> 1;
            ulonglong2 aA = *(const ulonglong2*)&Asb[r0 * AS_STRIDE + k4];
            ulonglong2 aB = *(const ulonglong2*)&Asb[(r0 + 1) * AS_STRIDE + k4];
            ulonglong2 w00 = *(const ulonglong2*)&Wsb[kp * 64 + c0 * 2];
            ulonglong2 w01 = *(const ulonglong2*)&Wsb[kp * 64 + c0 * 2 + 4];
            ulonglong2 w10 = *(const ulonglong2*)&Wsb[(kp + 1) * 64 + c0 * 2];
            ulonglong2 w11 = *(const ulonglong2*)&Wsb[(kp + 1) * 64 + c0 * 2 + 4];

            ffma2(acc[0][0], aA.x, w00.x); ffma2(acc[0][1], aA.x, w00.y);
            ffma2(acc[0][2], aA.x, w01.x); ffma2(acc[0][3], aA.x, w01.y);
            ffma2(acc[0][0], aA.y, w10.x); ffma2(acc[0][1], aA.y, w10.y);
            ffma2(acc[0][2], aA.y, w11.x); ffma2(acc[0][3], aA.y, w11.y);

            ffma2(acc[1][0], aB.x, w00.x); ffma2(acc[1][1], aB.x, w00.y);
            ffma2(acc[1][2], aB.x, w01.x); ffma2(acc[1][3], aB.x, w01.y);
            ffma2(acc[1][0], aB.y, w10.x); ffma2(acc[1][1], aB.y, w10.y);
            ffma2(acc[1][2], aB.y, w11.x); ffma2(acc[1][3], aB.y, w11.y);
        }
        __syncthreads();   // tile consumed; next prefetch may overwrite
    }

    // ---- in-register LSTM cell update: thread's 4 cols = gates (i,j,f,o) of unit u
    const int u = cta * 8 + ct;
    const float bi = bias[u], bj = bias[1024 + u],
                bf = bias[2048 + u], bo = bias[3072 + u];
    #pragma unroll
    for (int r = 0; r < 2; r++) {
        const int row = r0 + r;
        float zi = sumf2(acc[r][0]) + bi;
        float zj = sumf2(acc[r][1]) + bj;
        float zf = sumf2(acc[r][2]) + bf;
        float zo = sumf2(acc[r][3]) + bo;
        float co = Cold[row * U_DIM + u];
        float cn = co * sigf(zf + 1.0f) + sigf(zi) * tanhf(zj);
        float hn = sigf(zo) * tanhf(cn);
        Cnew[row * U_DIM + u] = cn;
        Hnew[row * U_DIM + u] = hn;
    }
}

// ---------------- fused dense + layernorm + relu + emit ----------------
__device__ __forceinline__ void dense_ln_phase(
    const float* __restrict__ H2, const float* __restrict__ Wd,
    const float* __restrict__ bd,
    const float* __restrict__ gamma, const float* __restrict__ beta,
    float* __restrict__ out, float* h2s, float* red, int t, int cta, int tid)
{
    if (cta >= B_ROWS) return;
    const int row = cta;

    *(float4*)&h2s[tid * 4] = *(const float4*)&H2[(size_t)row * U_DIM + tid * 4];
    __syncthreads();

    float acc = 0.0f;
    #pragma unroll 8
    for (int k = 0; k < U_DIM; k++)
        acc = fmaf(h2s[k], Wd[(size_t)k * F_DIM + tid], acc);
    float v = acc + bd[tid];

    red[tid] = v; __syncthreads();
    #pragma unroll
    for (int s = 128; s > 0; s >>= 1) {
        if (tid < s) red[tid] += red[tid + s];
        __syncthreads();
    }
    float mu = red[0] * (1.0f / 256.0f);
    __syncthreads();

    float d = v - mu;
    red[tid] = d * d; __syncthreads();
    #pragma unroll
    for (int s = 128; s > 0; s >>= 1) {
        if (tid < s) red[tid] += red[tid + s];
        __syncthreads();
    }
    float var = red[0] * (1.0f / 256.0f);

    float o = d * rsqrtf(var + 1e-12f) * gamma[tid] + beta[tid];
    o = fmaxf(o, 0.0f);
    g_emit[row * F_DIM + tid] = o;
    out[(size_t)row * T_STEPS * F_DIM + (size_t)t * F_DIM + tid] = o;
}

// ---------------- persistent kernel ----------------
__global__ void __launch_bounds__(NT, 1) lstm_persistent(
    const float* __restrict__ input, const unsigned char* __restrict__ condb,
    const float* __restrict__ b0, const float* __restrict__ b1,
    const float* __restrict__ b2,
    const float* __restrict__ Wd, const float* __restrict__ bd,
    const float* __restrict__ gamma, const float* __restrict__ beta,
    float* __restrict__ out)
{
    extern __shared__ char dynsmem[];
    float* Ash = (float*)dynsmem;
    float* Wsh = (float*)(dynsmem + AS_BYTES);
    float* h2s = (float*)dynsmem;                 // dense reuses A region
    float* red = (float*)(dynsmem + 8192);
    const uint32_t as_u32 = (uint32_t)__cvta_generic_to_shared(Ash);
    const uint32_t ws_u32 = (uint32_t)__cvta_generic_to_shared(Wsh);

    const int cta = blockIdx.x, tid = threadIdx.x;

    const float* Wr0 = g_Wr;
    const float* Wr1 = g_Wr + (size_t)1280 * 4096;
    const float* Wr2 = g_Wr + (size_t)(1280 + 2048) * 4096;

    // detect dtype of conditioned_lst: bool-u8 vs int32 vs float32
    int p1 = 0, p23 = 0;
    for (int i = tid; i < T_STEPS; i += NT) {
        unsigned char bv = condb[i];
        if (bv != 0) {
            if ((i & 3) == 1) p1 = 1;
            if ((i & 3) >= 2) p23 = 1;
        }
    }
    const int is_u8  = __syncthreads_or(p1);
    const int is_f32 = __syncthreads_or(p23) && !is_u8;
    const int*   cond32 = (const int*)condb;
    const float* condf  = (const float*)condb;

    {   // zero init ping-pong state
        float* hflat = &g_h[0][0][0][0];
        float* cflat = &g_c[0][0][0][0];
        const int tot = 2 * 3 * B_ROWS * U_DIM;
        for (int i = cta * NT + tid; i < tot; i += NB * NT) {
            hflat[i] = 0.0f; cflat[i] = 0.0f;
        }
    }
    grid_barrier();

    for (int t = 0; t < T_STEPS; t++) {
        const int p = t & 1, q = p ^ 1;
        int cv;
        if (is_u8)       cv = (int)condb[t];
        else if (is_f32) cv = (condf[t] != 0.0f);
        else             cv = cond32[t];
        const bool  use_in = (t == 0) || (cv != 0);
        const float* x  = use_in ? (input + (size_t)t * F_DIM) : g_emit;
        const int   ldx = use_in ? (T_STEPS * F_DIM) : F_DIM;

        layer_phase(x, ldx, F_DIM, &g_h[q][0][0][0], Wr0, b0,
                    &g_c[q][0][0][0], &g_c[p][0][0][0], &g_h[p][0][0][0],
                    Ash, Wsh, as_u32, ws_u32, cta, tid);
        grid_barrier();

        layer_phase(&g_h[p][0][0][0], U_DIM, U_DIM, &g_h[q][1][0][0], Wr1, b1,
                    &g_c[q][1][0][0], &g_c[p][1][0][0], &g_h[p][1][0][0],
                    Ash, Wsh, as_u32, ws_u32, cta, tid);
        grid_barrier();

        layer_phase(&g_h[p][1][0][0], U_DIM, U_DIM, &g_h[q][2][0][0], Wr2, b2,
                    &g_c[q][2][0][0], &g_c[p][2][0][0], &g_h[p][2][0][0],
                    Ash, Wsh, as_u32, ws_u32, cta, tid);
        grid_barrier();

        dense_ln_phase(&g_h[p][2][0][0], Wd, bd, gamma, beta, out,
                       h2s, red, t, cta, tid);
        grid_barrier();
    }
}

extern "C" void kernel_launch(void* const* d_in, const int* in_sizes, int n_in,
                              void* d_out, int out_size) {
    (void)in_sizes; (void)n_in; (void)out_size;

    float* Wr0 = nullptr;
    cudaGetSymbolAddress((void**)&Wr0, g_Wr);
    float* Wr1 = Wr0 + (size_t)1280 * 4096;
    float* Wr2 = Wr0 + (size_t)(1280 + 2048) * 4096;

    const int t0 = 1280 * 4096, t1 = 2048 * 4096;
    reorder_w<<<(t0 + 255) / 256, 256>>>((const float*)d_in[2], Wr0, t0);
    reorder_w<<<(t1 + 255) / 256, 256>>>((const float*)d_in[4], Wr1, t1);
    reorder_w<<<(t1 + 255) / 256, 256>>>((const float*)d_in[6], Wr2, t1);

    cudaFuncSetAttribute(lstm_persistent,
                         cudaFuncAttributeMaxDynamicSharedMemorySize, SMEM_TOTAL);

    lstm_persistent<<<NB, NT, SMEM_TOTAL>>>(
        (const float*)d_in[0], (const unsigned char*)d_in[1],
        (const float*)d_in[3], (const float*)d_in[5], (const float*)d_in[7],
        (const float*)d_in[8], (const float*)d_in[9],
        (const float*)d_in[10], (const float*)d_in[11],
        (float*)d_out);
}